// round 8
// baseline (speedup 1.0000x reference)
#include <cuda_runtime.h>
#include <cstdint>

// QuantizationLayer: out[i*4 + {0..3}] = bits (MSB-first) of round_half_even(x[i]*16 - 0.5)
// x: (32768, 512) f32 in [0,1)  ->  out: (32768, 2048) f32 of {0.0, 1.0}
//
// PERSISTENT grid-stride streaming kernel (single wave, no CTA churn):
//   grid = 912 CTAs x 256 thr; each CTA loops over pair-tiles with grid stride.
// Per pair: one float2 load (.cs, 256B/warp LDG.64) -> one 256-bit v8 store
// (1KB/warp STG.256, default write-back). 2 pairs in flight per iteration.

#define THREADS 256
#define PAIRS_PER_THREAD 2                      // 4 elements / thread / iter
#define TILE_PAIRS (THREADS * PAIRS_PER_THREAD) // 512 pairs / CTA / iter
#define GRID 912                                // 152 SMs * 6 CTAs: one wave

__device__ __forceinline__ void quant_pair_store(float2 v, float* gptr) {
    int c0 = ((int)rintf(fmaf(v.x, 16.0f, -0.5f))) & 15;
    int c1 = ((int)rintf(fmaf(v.y, 16.0f, -0.5f))) & 15;

    float b0 = (float)((c0 >> 3) & 1);
    float b1 = (float)((c0 >> 2) & 1);
    float b2 = (float)((c0 >> 1) & 1);
    float b3 = (float)(c0 & 1);
    float b4 = (float)((c1 >> 3) & 1);
    float b5 = (float)((c1 >> 2) & 1);
    float b6 = (float)((c1 >> 1) & 1);
    float b7 = (float)(c1 & 1);

#if __CUDA_ARCH__ >= 1000
    asm volatile(
        "st.global.v8.f32 [%0], {%1, %2, %3, %4, %5, %6, %7, %8};"
        :: "l"(gptr),
           "f"(b0), "f"(b1), "f"(b2), "f"(b3),
           "f"(b4), "f"(b5), "f"(b6), "f"(b7)
        : "memory");
#else
    ((float4*)gptr)[0] = make_float4(b0, b1, b2, b3);
    ((float4*)gptr)[1] = make_float4(b4, b5, b6, b7);
#endif
}

__global__ void __launch_bounds__(THREADS)
quant_unpack_kernel(const float2* __restrict__ x2,
                    float* __restrict__ out,
                    int n_pairs) {
    const int stride = gridDim.x * TILE_PAIRS;
    int base = blockIdx.x * TILE_PAIRS + threadIdx.x;

    // Main persistent loop: full tiles, no per-element guards.
    for (; base + (PAIRS_PER_THREAD - 1) * THREADS < n_pairs; base += stride) {
        float2 v[PAIRS_PER_THREAD];
#pragma unroll
        for (int k = 0; k < PAIRS_PER_THREAD; k++)
            v[k] = __ldcs(x2 + base + k * THREADS);

#pragma unroll
        for (int k = 0; k < PAIRS_PER_THREAD; k++) {
            int p = base + k * THREADS;
            quant_pair_store(v[k], out + (size_t)p * 8);
        }
    }

    // Tail (empty for n_pairs = 8,388,608 since it's a multiple of stride granularity)
#pragma unroll
    for (int k = 0; k < PAIRS_PER_THREAD; k++) {
        int p = base + k * THREADS;
        if (p < n_pairs) {
            float2 v = __ldcs(x2 + p);
            quant_pair_store(v, out + (size_t)p * 8);
        }
    }
}

extern "C" void kernel_launch(void* const* d_in, const int* in_sizes, int n_in,
                              void* d_out, int out_size) {
    const float* x = (const float*)d_in[0];
    float* out = (float*)d_out;
    int n = in_sizes[0];        // 16,777,216 (even)
    int n_pairs = n >> 1;       // 8,388,608

    int tiles = (n_pairs + TILE_PAIRS - 1) / TILE_PAIRS;
    int grid = (tiles < GRID) ? tiles : GRID;
    quant_unpack_kernel<<<grid, THREADS>>>((const float2*)x, out, n_pairs);
}

// round 9
// speedup vs baseline: 1.1469x; 1.1469x over previous
#include <cuda_runtime.h>
#include <cstdint>

// QuantizationLayer: out[i*4 + {0..3}] = bits (MSB-first) of round_half_even(x[i]*16 - 0.5)
// x: (32768, 512) f32 in [0,1)  ->  out: (32768, 2048) f32 of {0.0, 1.0}
//
// Streaming kernel at the mixed read/write HBM ceiling (~6.4 TB/s effective).
// Per thread: 4 independent float2 loads (MLP_p1=4, each 512B/warp LDG.64,
// .cs read-once) -> 4 x 256-bit v8 stores (each 2KB/warp STG.256, default
// write-back). 8 elements/thread, 256 thr/block, 8192 blocks (launched grid,
// NOT persistent - fresh CTAs keep the LSU queue full across boundaries).

#define THREADS 256
#define PAIRS_PER_THREAD 4                      // 8 elements / thread
#define TILE_PAIRS (THREADS * PAIRS_PER_THREAD) // 1024 pairs / block

__device__ __forceinline__ void quant_pair_store(float2 v, float* gptr) {
    int c0 = ((int)rintf(fmaf(v.x, 16.0f, -0.5f))) & 15;
    int c1 = ((int)rintf(fmaf(v.y, 16.0f, -0.5f))) & 15;

    float b0 = (float)((c0 >> 3) & 1);
    float b1 = (float)((c0 >> 2) & 1);
    float b2 = (float)((c0 >> 1) & 1);
    float b3 = (float)(c0 & 1);
    float b4 = (float)((c1 >> 3) & 1);
    float b5 = (float)((c1 >> 2) & 1);
    float b6 = (float)((c1 >> 1) & 1);
    float b7 = (float)(c1 & 1);

#if __CUDA_ARCH__ >= 1000
    asm volatile(
        "st.global.v8.f32 [%0], {%1, %2, %3, %4, %5, %6, %7, %8};"
        :: "l"(gptr),
           "f"(b0), "f"(b1), "f"(b2), "f"(b3),
           "f"(b4), "f"(b5), "f"(b6), "f"(b7)
        : "memory");
#else
    ((float4*)gptr)[0] = make_float4(b0, b1, b2, b3);
    ((float4*)gptr)[1] = make_float4(b4, b5, b6, b7);
#endif
}

__global__ void __launch_bounds__(THREADS)
quant_unpack_kernel(const float2* __restrict__ x2,
                    float* __restrict__ out,
                    int n_pairs) {
    int base = blockIdx.x * TILE_PAIRS + threadIdx.x;

    if (base + (PAIRS_PER_THREAD - 1) * THREADS < n_pairs) {
        // Fast path (always taken for n = 16,777,216): front-batched loads.
        float2 v[PAIRS_PER_THREAD];
#pragma unroll
        for (int k = 0; k < PAIRS_PER_THREAD; k++)
            v[k] = __ldcs(x2 + base + k * THREADS);

#pragma unroll
        for (int k = 0; k < PAIRS_PER_THREAD; k++) {
            int p = base + k * THREADS;
            quant_pair_store(v[k], out + (size_t)p * 8);
        }
    } else {
        // Tail path
#pragma unroll
        for (int k = 0; k < PAIRS_PER_THREAD; k++) {
            int p = base + k * THREADS;
            if (p >= n_pairs) continue;
            float2 v = __ldcs(x2 + p);
            quant_pair_store(v, out + (size_t)p * 8);
        }
    }
}

extern "C" void kernel_launch(void* const* d_in, const int* in_sizes, int n_in,
                              void* d_out, int out_size) {
    const float* x = (const float*)d_in[0];
    float* out = (float*)d_out;
    int n = in_sizes[0];        // 16,777,216 (even)
    int n_pairs = n >> 1;       // 8,388,608

    int blocks = (n_pairs + TILE_PAIRS - 1) / TILE_PAIRS;  // 8192
    quant_unpack_kernel<<<blocks, THREADS>>>((const float2*)x, out, n_pairs);
}

// round 10
// speedup vs baseline: 1.1748x; 1.0243x over previous
#include <cuda_runtime.h>
#include <cstdint>

// QuantizationLayer: out[i*4 + {0..3}] = bits (MSB-first) of round_half_even(x[i]*16 - 0.5)
// x: (32768, 512) f32 in [0,1)  ->  out: (32768, 2048) f32 of {0.0, 1.0}
//
// Converged streaming kernel at the mixed read/write HBM ceiling
// (~6.4 TB/s effective = ~80% of 8 TB/s spec for a 1:4 R:W stream).
// Best-measured shape (R1): 4 elements/thread, blockDim-strided:
//   - 4 independent LDG.32 (.cs), each a coalesced 128B/warp, MLP_p1=4
//   - 4 STG.128, each a coalesced 512B/warp
// Bits produced with selects (no I2F).

#define ELEMS_PER_THREAD 4
#define THREADS 256
#define TILE (THREADS * ELEMS_PER_THREAD)

__device__ __forceinline__ float4 quant_bits(float v) {
    // round-half-to-even (rintf = RN nearest-even) matches jnp.round;
    // v*16 exact (pow2), -0.5 exact, code in [0,15].
    int c = ((int)rintf(fmaf(v, 16.0f, -0.5f))) & 15;
    float4 b;
    b.x = (c & 8) ? 1.0f : 0.0f;
    b.y = (c & 4) ? 1.0f : 0.0f;
    b.z = (c & 2) ? 1.0f : 0.0f;
    b.w = (c & 1) ? 1.0f : 0.0f;
    return b;
}

__global__ void __launch_bounds__(THREADS)
quant_unpack_kernel(const float* __restrict__ x,
                    float4* __restrict__ out,
                    int n) {
    int base = blockIdx.x * TILE + threadIdx.x;

    if (base + (ELEMS_PER_THREAD - 1) * THREADS < n) {
        // Fast path (always taken for n = 16,777,216): front-batched loads.
        float v[ELEMS_PER_THREAD];
#pragma unroll
        for (int k = 0; k < ELEMS_PER_THREAD; k++)
            v[k] = __ldcs(x + base + k * THREADS);

#pragma unroll
        for (int k = 0; k < ELEMS_PER_THREAD; k++)
            __stcs(out + base + k * THREADS, quant_bits(v[k]));
    } else {
        // Tail path
#pragma unroll
        for (int k = 0; k < ELEMS_PER_THREAD; k++) {
            int i = base + k * THREADS;
            if (i < n)
                __stcs(out + i, quant_bits(__ldcs(x + i)));
        }
    }
}

extern "C" void kernel_launch(void* const* d_in, const int* in_sizes, int n_in,
                              void* d_out, int out_size) {
    const float* x = (const float*)d_in[0];
    float4* out = (float4*)d_out;
    int n = in_sizes[0];  // 16,777,216

    int blocks = (n + TILE - 1) / TILE;  // 16384
    quant_unpack_kernel<<<blocks, THREADS>>>(x, out, n);
}

// round 11
// speedup vs baseline: 1.1804x; 1.0048x over previous
#include <cuda_runtime.h>
#include <cstdint>

// QuantizationLayer: out[i*4 + {0..3}] = bits (MSB-first) of round_half_even(x[i]*16 - 0.5)
// x: (32768, 512) f32 in [0,1)  ->  out: (32768, 2048) f32 of {0.0, 1.0}
//
// Converged streaming kernel at the mixed read/write HBM ceiling
// (~6.4 TB/s effective = ~80% of 8 TB/s spec for a 1:4 R:W stream).
// Shape: 4 elements/thread, blockDim-strided:
//   - 4 independent LDG.32 (.cs), each a coalesced 128B/warp, MLP_p1=4
//   - 4 STG.128 (.cs), each a coalesced 512B/warp
// 128-thread CTAs: same warp supply, smaller per-CTA LDG front-batch
// (lower cross-CTA L1tex-queue spread), finer wave quantization.

#define ELEMS_PER_THREAD 4
#define THREADS 128
#define TILE (THREADS * ELEMS_PER_THREAD)

__device__ __forceinline__ float4 quant_bits(float v) {
    // round-half-to-even (rintf = RN nearest-even) matches jnp.round;
    // v*16 exact (pow2), -0.5 exact, code in [0,15].
    int c = ((int)rintf(fmaf(v, 16.0f, -0.5f))) & 15;
    float4 b;
    b.x = (c & 8) ? 1.0f : 0.0f;
    b.y = (c & 4) ? 1.0f : 0.0f;
    b.z = (c & 2) ? 1.0f : 0.0f;
    b.w = (c & 1) ? 1.0f : 0.0f;
    return b;
}

__global__ void __launch_bounds__(THREADS)
quant_unpack_kernel(const float* __restrict__ x,
                    float4* __restrict__ out,
                    int n) {
    int base = blockIdx.x * TILE + threadIdx.x;

    if (base + (ELEMS_PER_THREAD - 1) * THREADS < n) {
        // Fast path (always taken for n = 16,777,216): front-batched loads.
        float v[ELEMS_PER_THREAD];
#pragma unroll
        for (int k = 0; k < ELEMS_PER_THREAD; k++)
            v[k] = __ldcs(x + base + k * THREADS);

#pragma unroll
        for (int k = 0; k < ELEMS_PER_THREAD; k++)
            __stcs(out + base + k * THREADS, quant_bits(v[k]));
    } else {
        // Tail path
#pragma unroll
        for (int k = 0; k < ELEMS_PER_THREAD; k++) {
            int i = base + k * THREADS;
            if (i < n)
                __stcs(out + i, quant_bits(__ldcs(x + i)));
        }
    }
}

extern "C" void kernel_launch(void* const* d_in, const int* in_sizes, int n_in,
                              void* d_out, int out_size) {
    const float* x = (const float*)d_in[0];
    float4* out = (float4*)d_out;
    int n = in_sizes[0];  // 16,777,216

    int blocks = (n + TILE - 1) / TILE;  // 32768
    quant_unpack_kernel<<<blocks, THREADS>>>(x, out, n);
}